// round 8
// baseline (speedup 1.0000x reference)
#include <cuda_runtime.h>
#include <math.h>

#define HH 1024
#define WW 1024
#define BIGF 1e6f
#define FULLMASK 0xffffffffu

// Scratch (allocation-free per harness rules)
__device__ unsigned char d_edges8[2][HH * WW];  // binary edge masks (0/1)
__device__ float d_g2[2][HH * WW];              // squared per-row 1D distances
#define TOTB (2 * HH)                           // 2048 blocks in the EDT pass
__device__ float d_partials[TOTB];
__device__ int d_count;                         // zero-init; self-resetting

// ---------------------------------------------------------------------------
// Kernel A+B fused: per-warp row processing.
//   1) edges = seg - eroded, eroded = (3x3 zero-padded box sum == 9).
//      Since seg in {0,1} and eroded=1 only where seg=1, edges is a 0/1 mask.
//      Computed inline: vertical 3-row sums + horizontal 3-tap via shfl.
//   2) per-row 1D feature distance, exactly mirroring the reference:
//        left  = x - cummax(feat ? x : -BIG)        (forward inclusive)
//        right = cummin_rev(feat ? x : BIG) - x     (reverse inclusive)
//        g     = min(left, right, BIG);   store g*g
//      register-local segmented scan + 5-step shfl Kogge-Stone carry.
// One warp per (image,row); lane owns 32 contiguous columns. No barriers.
// NOTE: bare launch_bounds only — no min-blocks forcing, which would cap
// registers and spill the register-resident row arrays to local memory.
// ---------------------------------------------------------------------------
__global__ __launch_bounds__(128)
void edges_row_dist_kernel(const float* __restrict__ pred,
                           const float* __restrict__ targ) {
    int warp = blockIdx.x * (blockDim.x >> 5) + (threadIdx.x >> 5);
    int lane = threadIdx.x & 31;
    int m = warp >> 10;              // image
    int y = warp & (HH - 1);         // row
    int base = lane * 32;            // first column owned by this lane
    const float* src = (m == 0) ? pred : targ;

    // ---- load center row + compute vertical 3-row sums ----
    float c[32], e[32];
    bool yint = (y > 0) && (y < HH - 1);
    if (yint) {
        float vs[32];
        const float4* cr = (const float4*)(src + y * WW + base);
        const float4* tr = (const float4*)(src + (y - 1) * WW + base);
        const float4* br = (const float4*)(src + (y + 1) * WW + base);
        #pragma unroll
        for (int k = 0; k < 8; k++) {
            float4 c4 = cr[k], t4 = tr[k], b4 = br[k];
            c[4 * k + 0] = c4.x; c[4 * k + 1] = c4.y;
            c[4 * k + 2] = c4.z; c[4 * k + 3] = c4.w;
            vs[4 * k + 0] = t4.x + c4.x + b4.x;
            vs[4 * k + 1] = t4.y + c4.y + b4.y;
            vs[4 * k + 2] = t4.z + c4.z + b4.z;
            vs[4 * k + 3] = t4.w + c4.w + b4.w;
        }
        // cross-lane neighbors for the horizontal 3-tap
        float vsl = __shfl_up_sync(FULLMASK, vs[31], 1);   // lane-1's vs[31]
        float vsr = __shfl_down_sync(FULLMASK, vs[0], 1);  // lane+1's vs[0]
        #pragma unroll
        for (int k = 0; k < 32; k++) {
            float l = (k == 0) ? vsl : vs[k - 1];
            float r = (k == 31) ? vsr : vs[k + 1];
            float hsum = l + vs[k] + r;
            int col = base + k;
            bool interior = (col > 0) && (col < WW - 1);
            float eroded = (interior && hsum == 9.0f) ? 1.0f : 0.0f;
            e[k] = c[k] - eroded;
        }
    } else {
        // boundary rows: 3x3 zero-padded sum < 9 always -> eroded = 0
        const float4* cr = (const float4*)(src + y * WW + base);
        #pragma unroll
        for (int k = 0; k < 8; k++) {
            float4 c4 = cr[k];
            e[4 * k + 0] = c4.x; e[4 * k + 1] = c4.y;
            e[4 * k + 2] = c4.z; e[4 * k + 3] = c4.w;
        }
    }

    // ---- store edges as a byte mask (needed by cross-weighting pass) ----
    {
        unsigned int w[8];
        #pragma unroll
        for (int q = 0; q < 8; q++) {
            unsigned int b0 = (e[4 * q + 0] != 0.0f) ? 1u : 0u;
            unsigned int b1 = (e[4 * q + 1] != 0.0f) ? 1u : 0u;
            unsigned int b2 = (e[4 * q + 2] != 0.0f) ? 1u : 0u;
            unsigned int b3 = (e[4 * q + 3] != 0.0f) ? 1u : 0u;
            w[q] = b0 | (b1 << 8) | (b2 << 16) | (b3 << 24);
        }
        uint4* eo = (uint4*)(d_edges8[m] + y * WW + base);
        eo[0] = make_uint4(w[0], w[1], w[2], w[3]);
        eo[1] = make_uint4(w[4], w[5], w[6], w[7]);
    }

    // ---- forward inclusive cummax of (feat ? col : -BIG) ----
    float lmax[32];
    float run = -BIGF;
    #pragma unroll
    for (int k = 0; k < 32; k++) {
        float v = (e[k] != 0.0f) ? (float)(base + k) : -BIGF;
        run = fmaxf(run, v);
        lmax[k] = run;
    }
    float inc = run;                 // lane total
    #pragma unroll
    for (int d = 1; d < 32; d <<= 1) {
        float o = __shfl_up_sync(FULLMASK, inc, d);
        if (lane >= d) inc = fmaxf(inc, o);
    }
    float pre = __shfl_up_sync(FULLMASK, inc, 1);   // exclusive prefix max
    if (lane == 0) pre = -BIGF;

    // ---- reverse inclusive cummin of (feat ? col : BIG) ----
    float rmin[32];
    float rrun = BIGF;
    #pragma unroll
    for (int k = 31; k >= 0; k--) {
        float v = (e[k] != 0.0f) ? (float)(base + k) : BIGF;
        rrun = fminf(rrun, v);
        rmin[k] = rrun;
    }
    float incm = rrun;               // lane total (suffix min of lane segment)
    #pragma unroll
    for (int d = 1; d < 32; d <<= 1) {
        float o = __shfl_down_sync(FULLMASK, incm, d);
        if (lane + d < 32) incm = fminf(incm, o);
    }
    float suf = __shfl_down_sync(FULLMASK, incm, 1); // exclusive suffix min
    if (lane == 31) suf = BIGF;

    // ---- combine + vectorized store of g^2 ----
    float4* out4 = (float4*)(d_g2[m] + y * WW + base);
    #pragma unroll
    for (int k = 0; k < 8; k++) {
        float g[4];
        #pragma unroll
        for (int u = 0; u < 4; u++) {
            int idx = 4 * k + u;
            float col = (float)(base + idx);
            float left = col - fmaxf(lmax[idx], pre);
            float right = fminf(rmin[idx], suf) - col;
            g[u] = fminf(fminf(left, right), BIGF);
        }
        float4 o;
        o.x = g[0] * g[0]; o.y = g[1] * g[1];
        o.z = g[2] * g[2]; o.w = g[3] * g[3];
        out4[k] = o;
    }
}

// ---------------------------------------------------------------------------
// Kernel C: exact column EDT (4 columns per thread, float4) + fused loss
// weighting + grid-wide "last block done" reduction + sigmoid.
// D2(i,j) = min_k g2(k,j) + (i-k)^2. Any candidate with dk^2 >= bmax
// satisfies g2+dk^2 >= dk^2 >= bmax >= b_col for every column, and b only
// decreases afterward, so the shared early-exit is EXACT. One 256-thread
// block per (row i, image m); thread owns columns [4*tx, 4*tx+4).
// ---------------------------------------------------------------------------
__global__ __launch_bounds__(256)
void edt_loss_kernel(float* __restrict__ out) {
    int tx = threadIdx.x;
    int j4 = tx * 4;                 // first of 4 columns
    int i = blockIdx.x;
    int m = blockIdx.y;
    const float* g2 = d_g2[m];

    // hoisted: other-image edge mask load overlaps with the window walk
    uchar4 e = *(const uchar4*)(d_edges8[1 - m] + i * WW + j4);

    float4 b = *(const float4*)(g2 + i * WW + j4);   // k = i candidates
    float bmax = fmaxf(fmaxf(b.x, b.y), fmaxf(b.z, b.w));

    float dk2 = 1.0f;                // dk^2, carried incrementally
    for (int dk = 1; dk < HH; dk++) {
        if (dk2 >= bmax) break;      // exact early-exit bound (see above)
        int up = i - dk, dn = i + dk;
        if (up >= 0) {
            float4 v = *(const float4*)(g2 + up * WW + j4);
            b.x = fminf(b.x, v.x + dk2); b.y = fminf(b.y, v.y + dk2);
            b.z = fminf(b.z, v.z + dk2); b.w = fminf(b.w, v.w + dk2);
        }
        if (dn < HH) {
            float4 v = *(const float4*)(g2 + dn * WW + j4);
            b.x = fminf(b.x, v.x + dk2); b.y = fminf(b.y, v.y + dk2);
            b.z = fminf(b.z, v.z + dk2); b.w = fminf(b.w, v.w + dk2);
        }
        bmax = fmaxf(fmaxf(b.x, b.y), fmaxf(b.z, b.w));
        dk2 += 2.0f * (float)dk + 1.0f;   // (dk+1)^2 = dk^2 + 2dk + 1
    }

    // cross-weighting: pred_dt weighted by target edge mask and vice versa
    float val = (e.x ? sqrtf(b.x) : 0.0f) + (e.y ? sqrtf(b.y) : 0.0f)
              + (e.z ? sqrtf(b.z) : 0.0f) + (e.w ? sqrtf(b.w) : 0.0f);

    // deterministic block reduction: per-warp shfl tree + fixed-order sum
    #pragma unroll
    for (int d = 16; d > 0; d >>= 1)
        val += __shfl_down_sync(FULLMASK, val, d);

    __shared__ float wsum[8];
    __shared__ bool is_last;
    int lane = tx & 31;
    int wid = tx >> 5;
    if (lane == 0) wsum[wid] = val;
    __syncthreads();
    if (tx == 0) {
        float s = 0.0f;
        #pragma unroll
        for (int w = 0; w < 8; w++) s += wsum[w];
        int bid = blockIdx.y * gridDim.x + blockIdx.x;
        d_partials[bid] = s;
        __threadfence();                     // partial visible before count
        int old = atomicAdd(&d_count, 1);
        is_last = (old == TOTB - 1);
    }
    __syncthreads();

    // ---- last block: deterministic fixed-order final reduction + sigmoid ----
    if (is_last) {
        __threadfence();                     // acquire all partials
        __shared__ double sh[256];
        double s = 0.0;
        for (int k = tx; k < TOTB; k += 256)
            s += (double)d_partials[k];
        sh[tx] = s;
        __syncthreads();
        for (int st = 128; st > 0; st >>= 1) {
            if (tx < st) sh[tx] += sh[tx + st];
            __syncthreads();
        }
        if (tx == 0) {
            double loss = sh[0] / (2.0 * (double)HH * (double)WW);
            out[0] = (float)(1.0 / (1.0 + exp(-loss)));
            d_count = 0;                     // reset for next graph replay
        }
    }
}

// ---------------------------------------------------------------------------
extern "C" void kernel_launch(void* const* d_in, const int* in_sizes, int n_in,
                              void* d_out, int out_size) {
    const float* pred = (const float*)d_in[0];
    const float* targ = (const float*)d_in[1];
    float* out = (float*)d_out;

    // 2048 rows total (2 images x 1024 rows), one warp per row, 4 warps/block
    edges_row_dist_kernel<<<2 * HH / 4, 128>>>(pred, targ);

    // one 256-thread block per (row, image); 4 columns per thread
    edt_loss_kernel<<<dim3(HH, 2), 256>>>(out);
}

// round 10
// speedup vs baseline: 1.0795x; 1.0795x over previous
#include <cuda_runtime.h>
#include <math.h>

#define HH 1024
#define WW 1024
#define BIGF 1e6f
#define FULLMASK 0xffffffffu

// Scratch (allocation-free per harness rules)
__device__ unsigned char d_edges8[2][HH * WW];  // binary edge masks (0/1)
__device__ float d_g2[2][HH * WW];              // squared per-row 1D distances
#define TOTB (2 * HH)                           // 2048 blocks in the EDT pass
__device__ float d_partials[TOTB];
__device__ int d_count;                         // zero-init; self-resetting

// Reflect an out-of-range row index into [0, HH-1]. For every reflection at
// shell dk, |i - r'| <= dk, so g2[r'] + dk^2 >= g2[r'] + (i-r')^2 (a true
// candidate): merges through it only over-estimate and can never drop any
// column below the exact EDT value.
__device__ __forceinline__ int refl(int r) {
    if (r < 0) r = -r;
    if (r > HH - 1) { r = 2 * (HH - 1) - r; if (r < 0) r = -r; }
    return r;
}

// ---------------------------------------------------------------------------
// Kernel A+B fused: one 256-thread block per (row i, image m); each thread
// owns 4 contiguous columns (low register pressure — no spills).
//   1) edges = seg - eroded, eroded = (3x3 zero-padded box sum == 9).
//      Vertical 3-row sums in registers; horizontal 3-tap via padded smem.
//   2) per-row 1D feature distance, exactly mirroring the reference:
//        left  = x - cummax(feat ? x : -BIG)        (forward inclusive)
//        right = cummin_rev(feat ? x : BIG) - x     (reverse inclusive)
//        g     = min(left, right, BIG);   store g*g
//      3-level scan: thread-local (4) -> warp shfl (5 steps) -> 8 warp totals.
// ---------------------------------------------------------------------------
__global__ __launch_bounds__(256)
void edges_row_dist_kernel(const float* __restrict__ pred,
                           const float* __restrict__ targ) {
    int i = blockIdx.x;              // row
    int m = blockIdx.y;              // image
    int tx = threadIdx.x;
    int j4 = tx * 4;                 // first of 4 columns
    int lane = tx & 31;
    int wid = tx >> 5;
    const float* src = (m == 0) ? pred : targ;

    __shared__ float svs[WW + 2];    // padded vertical sums (+1 offset)
    __shared__ float wmax[8], wmin[8];

    float4 c4 = *(const float4*)(src + i * WW + j4);
    float e0, e1, e2, e3;
    bool yint = (i > 0) && (i < HH - 1);   // block-uniform
    if (yint) {
        float4 t4 = *(const float4*)(src + (i - 1) * WW + j4);
        float4 b4 = *(const float4*)(src + (i + 1) * WW + j4);
        svs[j4 + 1] = t4.x + c4.x + b4.x;
        svs[j4 + 2] = t4.y + c4.y + b4.y;
        svs[j4 + 3] = t4.z + c4.z + b4.z;
        svs[j4 + 4] = t4.w + c4.w + b4.w;
        if (tx == 0) { svs[0] = 0.0f; svs[WW + 1] = 0.0f; }
        __syncthreads();
        float h0 = svs[j4 + 0] + svs[j4 + 1] + svs[j4 + 2];
        float h1 = svs[j4 + 1] + svs[j4 + 2] + svs[j4 + 3];
        float h2 = svs[j4 + 2] + svs[j4 + 3] + svs[j4 + 4];
        float h3 = svs[j4 + 3] + svs[j4 + 4] + svs[j4 + 5];
        bool in0 = (j4 + 0 > 0) && (j4 + 0 < WW - 1);
        bool in3 = (j4 + 3 < WW - 1);  // j4+1, j4+2 always interior cols
        e0 = c4.x - ((in0 && h0 == 9.0f) ? 1.0f : 0.0f);
        e1 = c4.y - ((h1 == 9.0f) ? 1.0f : 0.0f);
        e2 = c4.z - ((h2 == 9.0f) ? 1.0f : 0.0f);
        e3 = c4.w - ((in3 && h3 == 9.0f) ? 1.0f : 0.0f);
    } else {
        // boundary rows: 3x3 zero-padded sum < 9 always -> eroded = 0
        e0 = c4.x; e1 = c4.y; e2 = c4.z; e3 = c4.w;
    }

    // ---- store edges as a byte mask (needed by cross-weighting pass) ----
    {
        unsigned int w = ((e0 != 0.0f) ? 1u : 0u)
                       | ((e1 != 0.0f) ? 0x100u : 0u)
                       | ((e2 != 0.0f) ? 0x10000u : 0u)
                       | ((e3 != 0.0f) ? 0x1000000u : 0u);
        *(unsigned int*)(d_edges8[m] + i * WW + j4) = w;
    }

    // ---- forward inclusive cummax of (feat ? col : -BIG) ----
    float l0, l1, l2, l3;
    {
        float run = -BIGF;
        run = fmaxf(run, (e0 != 0.0f) ? (float)(j4 + 0) : -BIGF); l0 = run;
        run = fmaxf(run, (e1 != 0.0f) ? (float)(j4 + 1) : -BIGF); l1 = run;
        run = fmaxf(run, (e2 != 0.0f) ? (float)(j4 + 2) : -BIGF); l2 = run;
        run = fmaxf(run, (e3 != 0.0f) ? (float)(j4 + 3) : -BIGF); l3 = run;
    }
    float inc = l3;                  // thread total
    #pragma unroll
    for (int d = 1; d < 32; d <<= 1) {
        float o = __shfl_up_sync(FULLMASK, inc, d);
        if (lane >= d) inc = fmaxf(inc, o);
    }
    if (lane == 31) wmax[wid] = inc;

    // ---- reverse inclusive cummin of (feat ? col : BIG) ----
    float r0, r1, r2, r3;
    {
        float run = BIGF;
        run = fminf(run, (e3 != 0.0f) ? (float)(j4 + 3) : BIGF); r3 = run;
        run = fminf(run, (e2 != 0.0f) ? (float)(j4 + 2) : BIGF); r2 = run;
        run = fminf(run, (e1 != 0.0f) ? (float)(j4 + 1) : BIGF); r1 = run;
        run = fminf(run, (e0 != 0.0f) ? (float)(j4 + 0) : BIGF); r0 = run;
    }
    float incm = r0;                 // thread total (suffix min)
    #pragma unroll
    for (int d = 1; d < 32; d <<= 1) {
        float o = __shfl_down_sync(FULLMASK, incm, d);
        if (lane + d < 32) incm = fminf(incm, o);
    }
    if (lane == 0) wmin[wid] = incm;
    __syncthreads();

    // cross-warp exclusive prefixes (8 iterations, register-resident)
    float pre = -BIGF, suf = BIGF;
    #pragma unroll
    for (int w = 0; w < 8; w++) {
        if (w < wid) pre = fmaxf(pre, wmax[w]);
        if (w > wid) suf = fminf(suf, wmin[w]);
    }
    // lane-level exclusive carries within the warp
    float lanePre = __shfl_up_sync(FULLMASK, inc, 1);
    if (lane == 0) lanePre = -BIGF;
    pre = fmaxf(pre, lanePre);
    float laneSuf = __shfl_down_sync(FULLMASK, incm, 1);
    if (lane == 31) laneSuf = BIGF;
    suf = fminf(suf, laneSuf);

    // ---- combine + vectorized store of g^2 ----
    float4 o;
    {
        float col0 = (float)(j4 + 0), col1 = (float)(j4 + 1);
        float col2 = (float)(j4 + 2), col3 = (float)(j4 + 3);
        float g0 = fminf(fminf(col0 - fmaxf(l0, pre), fminf(r0, suf) - col0), BIGF);
        float g1 = fminf(fminf(col1 - fmaxf(l1, pre), fminf(r1, suf) - col1), BIGF);
        float g2v = fminf(fminf(col2 - fmaxf(l2, pre), fminf(r2, suf) - col2), BIGF);
        float g3 = fminf(fminf(col3 - fmaxf(l3, pre), fminf(r3, suf) - col3), BIGF);
        o.x = g0 * g0; o.y = g1 * g1; o.z = g2v * g2v; o.w = g3 * g3;
    }
    *(float4*)(d_g2[m] + i * WW + j4) = o;
}

// ---------------------------------------------------------------------------
// Kernel C: exact column EDT, shells batched in pairs (4 independent float4
// loads per batch -> MLP 4, one exit check per 2 shells) + fused loss
// weighting + grid-wide "last block done" reduction + sigmoid.
// Exactness: exit when next shell's dk^2 >= bmax implies every unprocessed
// candidate >= each column's current best; reflected merges are
// over-estimates of true candidates (see refl()).
// ---------------------------------------------------------------------------
__global__ __launch_bounds__(256)
void edt_loss_kernel(float* __restrict__ out) {
    int tx = threadIdx.x;
    int j4 = tx * 4;                 // first of 4 columns
    int i = blockIdx.x;
    int m = blockIdx.y;
    const float* g2 = d_g2[m];

    // hoisted: other-image edge mask load overlaps with the window walk
    uchar4 e = *(const uchar4*)(d_edges8[1 - m] + i * WW + j4);

    float4 b = __ldg((const float4*)(g2 + i * WW + j4));   // k = i candidates
    float bmax = fmaxf(fmaxf(b.x, b.y), fmaxf(b.z, b.w));

    int dk = 1;
    float nxt2 = 1.0f;               // dk^2 of next unprocessed shell
    while (nxt2 < bmax) {
        float dk2a = nxt2;
        float dk2b = (float)((dk + 1) * (dk + 1));
        int u1 = refl(i - dk),     d1 = refl(i + dk);
        int u2 = refl(i - dk - 1), d2 = refl(i + dk + 1);
        // 4 independent loads, issued before any consumer
        float4 va = __ldg((const float4*)(g2 + u1 * WW + j4));
        float4 vb = __ldg((const float4*)(g2 + d1 * WW + j4));
        float4 vc = __ldg((const float4*)(g2 + u2 * WW + j4));
        float4 vd = __ldg((const float4*)(g2 + d2 * WW + j4));
        b.x = fminf(b.x, fminf(va.x, vb.x) + dk2a);
        b.y = fminf(b.y, fminf(va.y, vb.y) + dk2a);
        b.z = fminf(b.z, fminf(va.z, vb.z) + dk2a);
        b.w = fminf(b.w, fminf(va.w, vb.w) + dk2a);
        b.x = fminf(b.x, fminf(vc.x, vd.x) + dk2b);
        b.y = fminf(b.y, fminf(vc.y, vd.y) + dk2b);
        b.z = fminf(b.z, fminf(vc.z, vd.z) + dk2b);
        b.w = fminf(b.w, fminf(vc.w, vd.w) + dk2b);
        bmax = fmaxf(fmaxf(b.x, b.y), fmaxf(b.z, b.w));
        dk += 2;
        if (dk >= HH) break;
        nxt2 = (float)(dk * dk);
    }

    // cross-weighting: pred_dt weighted by target edge mask and vice versa
    float val = (e.x ? sqrtf(b.x) : 0.0f) + (e.y ? sqrtf(b.y) : 0.0f)
              + (e.z ? sqrtf(b.z) : 0.0f) + (e.w ? sqrtf(b.w) : 0.0f);

    // deterministic block reduction: per-warp shfl tree + fixed-order sum
    #pragma unroll
    for (int d = 16; d > 0; d >>= 1)
        val += __shfl_down_sync(FULLMASK, val, d);

    __shared__ float wsum[8];
    __shared__ bool is_last;
    int lane = tx & 31;
    int wid = tx >> 5;
    if (lane == 0) wsum[wid] = val;
    __syncthreads();
    if (tx == 0) {
        float s = 0.0f;
        #pragma unroll
        for (int w = 0; w < 8; w++) s += wsum[w];
        int bid = blockIdx.y * gridDim.x + blockIdx.x;
        d_partials[bid] = s;
        __threadfence();                     // partial visible before count
        int old = atomicAdd(&d_count, 1);
        is_last = (old == TOTB - 1);
    }
    __syncthreads();

    // ---- last block: deterministic fixed-order final reduction + sigmoid ----
    if (is_last) {
        __threadfence();                     // acquire all partials
        __shared__ double sh[256];
        double s = 0.0;
        for (int k = tx; k < TOTB; k += 256)
            s += (double)d_partials[k];
        sh[tx] = s;
        __syncthreads();
        for (int st = 128; st > 0; st >>= 1) {
            if (tx < st) sh[tx] += sh[tx + st];
            __syncthreads();
        }
        if (tx == 0) {
            double loss = sh[0] / (2.0 * (double)HH * (double)WW);
            out[0] = (float)(1.0 / (1.0 + exp(-loss)));
            d_count = 0;                     // reset for next graph replay
        }
    }
}

// ---------------------------------------------------------------------------
extern "C" void kernel_launch(void* const* d_in, const int* in_sizes, int n_in,
                              void* d_out, int out_size) {
    const float* pred = (const float*)d_in[0];
    const float* targ = (const float*)d_in[1];
    float* out = (float*)d_out;

    // one 256-thread block per (row, image) for both passes
    edges_row_dist_kernel<<<dim3(HH, 2), 256>>>(pred, targ);
    edt_loss_kernel<<<dim3(HH, 2), 256>>>(out);
}

// round 17
// speedup vs baseline: 1.1761x; 1.0894x over previous
#include <cuda_runtime.h>
#include <math.h>

#define HH 1024
#define WW 1024
#define BIGF 1e6f
#define FULLMASK 0xffffffffu

// Scratch (allocation-free per harness rules)
__device__ unsigned char d_edges8[2][HH * WW];  // binary edge masks (0/1)
__device__ float d_g2[2][HH * WW];              // squared per-row 1D distances
#define TOTB (2 * HH)                           // 2048 blocks in the EDT pass
__device__ float d_partials[TOTB];
__device__ int d_count;                         // zero-init; self-resetting

// Reflect an out-of-range row index into [0, HH-1]. For every reflection at
// shell dk, |i - r'| <= dk, so g2[r'] + dk^2 >= g2[r'] + (i-r')^2 (a true
// candidate): merges through it only over-estimate and can never drop any
// column below the exact EDT value.
__device__ __forceinline__ int refl(int r) {
    if (r < 0) r = -r;
    if (r > HH - 1) { r = 2 * (HH - 1) - r; if (r < 0) r = -r; }
    return r;
}

// ---------------------------------------------------------------------------
// Kernel A+B fused: one 256-thread block per (row i, image m); each thread
// owns 4 contiguous columns (low register pressure — no spills).
//   1) edges = seg - eroded, eroded = (3x3 zero-padded box sum == 9).
//      Vertical 3-row sums in registers; horizontal 3-tap via padded smem.
//   2) per-row 1D feature distance, exactly mirroring the reference:
//        left  = x - cummax(feat ? x : -BIG)        (forward inclusive)
//        right = cummin_rev(feat ? x : BIG) - x     (reverse inclusive)
//        g     = min(left, right, BIG);   store g*g
//      3-level scan: thread-local (4) -> warp shfl (5 steps) -> 8 warp totals.
// ---------------------------------------------------------------------------
__global__ __launch_bounds__(256)
void edges_row_dist_kernel(const float* __restrict__ pred,
                           const float* __restrict__ targ) {
    int i = blockIdx.x;              // row
    int m = blockIdx.y;              // image
    int tx = threadIdx.x;
    int j4 = tx * 4;                 // first of 4 columns
    int lane = tx & 31;
    int wid = tx >> 5;
    const float* src = (m == 0) ? pred : targ;

    __shared__ float svs[WW + 2];    // padded vertical sums (+1 offset)
    __shared__ float wmax[8], wmin[8];

    float4 c4 = *(const float4*)(src + i * WW + j4);
    float e0, e1, e2, e3;
    bool yint = (i > 0) && (i < HH - 1);   // block-uniform
    if (yint) {
        float4 t4 = *(const float4*)(src + (i - 1) * WW + j4);
        float4 b4 = *(const float4*)(src + (i + 1) * WW + j4);
        svs[j4 + 1] = t4.x + c4.x + b4.x;
        svs[j4 + 2] = t4.y + c4.y + b4.y;
        svs[j4 + 3] = t4.z + c4.z + b4.z;
        svs[j4 + 4] = t4.w + c4.w + b4.w;
        if (tx == 0) { svs[0] = 0.0f; svs[WW + 1] = 0.0f; }
        __syncthreads();
        float h0 = svs[j4 + 0] + svs[j4 + 1] + svs[j4 + 2];
        float h1 = svs[j4 + 1] + svs[j4 + 2] + svs[j4 + 3];
        float h2 = svs[j4 + 2] + svs[j4 + 3] + svs[j4 + 4];
        float h3 = svs[j4 + 3] + svs[j4 + 4] + svs[j4 + 5];
        bool in0 = (j4 + 0 > 0) && (j4 + 0 < WW - 1);
        bool in3 = (j4 + 3 < WW - 1);  // j4+1, j4+2 always interior cols
        e0 = c4.x - ((in0 && h0 == 9.0f) ? 1.0f : 0.0f);
        e1 = c4.y - ((h1 == 9.0f) ? 1.0f : 0.0f);
        e2 = c4.z - ((h2 == 9.0f) ? 1.0f : 0.0f);
        e3 = c4.w - ((in3 && h3 == 9.0f) ? 1.0f : 0.0f);
    } else {
        // boundary rows: 3x3 zero-padded sum < 9 always -> eroded = 0
        e0 = c4.x; e1 = c4.y; e2 = c4.z; e3 = c4.w;
    }

    // ---- store edges as a byte mask (needed by cross-weighting pass) ----
    {
        unsigned int w = ((e0 != 0.0f) ? 1u : 0u)
                       | ((e1 != 0.0f) ? 0x100u : 0u)
                       | ((e2 != 0.0f) ? 0x10000u : 0u)
                       | ((e3 != 0.0f) ? 0x1000000u : 0u);
        *(unsigned int*)(d_edges8[m] + i * WW + j4) = w;
    }

    // ---- forward inclusive cummax of (feat ? col : -BIG) ----
    float l0, l1, l2, l3;
    {
        float run = -BIGF;
        run = fmaxf(run, (e0 != 0.0f) ? (float)(j4 + 0) : -BIGF); l0 = run;
        run = fmaxf(run, (e1 != 0.0f) ? (float)(j4 + 1) : -BIGF); l1 = run;
        run = fmaxf(run, (e2 != 0.0f) ? (float)(j4 + 2) : -BIGF); l2 = run;
        run = fmaxf(run, (e3 != 0.0f) ? (float)(j4 + 3) : -BIGF); l3 = run;
    }
    float inc = l3;                  // thread total
    #pragma unroll
    for (int d = 1; d < 32; d <<= 1) {
        float o = __shfl_up_sync(FULLMASK, inc, d);
        if (lane >= d) inc = fmaxf(inc, o);
    }
    if (lane == 31) wmax[wid] = inc;

    // ---- reverse inclusive cummin of (feat ? col : BIG) ----
    float r0, r1, r2, r3;
    {
        float run = BIGF;
        run = fminf(run, (e3 != 0.0f) ? (float)(j4 + 3) : BIGF); r3 = run;
        run = fminf(run, (e2 != 0.0f) ? (float)(j4 + 2) : BIGF); r2 = run;
        run = fminf(run, (e1 != 0.0f) ? (float)(j4 + 1) : BIGF); r1 = run;
        run = fminf(run, (e0 != 0.0f) ? (float)(j4 + 0) : BIGF); r0 = run;
    }
    float incm = r0;                 // thread total (suffix min)
    #pragma unroll
    for (int d = 1; d < 32; d <<= 1) {
        float o = __shfl_down_sync(FULLMASK, incm, d);
        if (lane + d < 32) incm = fminf(incm, o);
    }
    if (lane == 0) wmin[wid] = incm;
    __syncthreads();

    // cross-warp exclusive prefixes (8 iterations, register-resident)
    float pre = -BIGF, suf = BIGF;
    #pragma unroll
    for (int w = 0; w < 8; w++) {
        if (w < wid) pre = fmaxf(pre, wmax[w]);
        if (w > wid) suf = fminf(suf, wmin[w]);
    }
    // lane-level exclusive carries within the warp
    float lanePre = __shfl_up_sync(FULLMASK, inc, 1);
    if (lane == 0) lanePre = -BIGF;
    pre = fmaxf(pre, lanePre);
    float laneSuf = __shfl_down_sync(FULLMASK, incm, 1);
    if (lane == 31) laneSuf = BIGF;
    suf = fminf(suf, laneSuf);

    // ---- combine + vectorized store of g^2 ----
    float4 o;
    {
        float col0 = (float)(j4 + 0), col1 = (float)(j4 + 1);
        float col2 = (float)(j4 + 2), col3 = (float)(j4 + 3);
        float g0 = fminf(fminf(col0 - fmaxf(l0, pre), fminf(r0, suf) - col0), BIGF);
        float g1 = fminf(fminf(col1 - fmaxf(l1, pre), fminf(r1, suf) - col1), BIGF);
        float g2v = fminf(fminf(col2 - fmaxf(l2, pre), fminf(r2, suf) - col2), BIGF);
        float g3 = fminf(fminf(col3 - fmaxf(l3, pre), fminf(r3, suf) - col3), BIGF);
        o.x = g0 * g0; o.y = g1 * g1; o.z = g2v * g2v; o.w = g3 * g3;
    }
    *(float4*)(d_g2[m] + i * WW + j4) = o;
}

// ---------------------------------------------------------------------------
// Kernel C: exact column EDT with UNCONDITIONAL shell-1 prefetch (mask, row i,
// rows i+-1 issued as 4 independent loads -> one exposed L2 latency for ~94%
// of warps), then a rare single-shell loop from dk=2 (entered by ~6% of
// warps). Fused loss weighting + grid-wide "last block done" reduction +
// sigmoid. Exactness: shell-1 merge is a true-candidate merge (reflection
// only over-estimates); exit when the next shell's dk^2 >= bmax implies all
// unprocessed candidates >= every column's current best.
// ---------------------------------------------------------------------------
__global__ __launch_bounds__(256)
void edt_loss_kernel(float* __restrict__ out) {
    int tx = threadIdx.x;
    int j4 = tx * 4;                 // first of 4 columns
    int i = blockIdx.x;
    int m = blockIdx.y;
    const float* g2 = d_g2[m];

    // ---- all init loads issued back-to-back (MLP 4, one exposed latency) ----
    uchar4 e = *(const uchar4*)(d_edges8[1 - m] + i * WW + j4);
    float4 b = __ldg((const float4*)(g2 + i * WW + j4));
    int u1 = refl(i - 1), dn1 = refl(i + 1);
    float4 va = __ldg((const float4*)(g2 + u1 * WW + j4));
    float4 vb = __ldg((const float4*)(g2 + dn1 * WW + j4));

    // merge shell 1 unconditionally
    b.x = fminf(b.x, fminf(va.x, vb.x) + 1.0f);
    b.y = fminf(b.y, fminf(va.y, vb.y) + 1.0f);
    b.z = fminf(b.z, fminf(va.z, vb.z) + 1.0f);
    b.w = fminf(b.w, fminf(va.w, vb.w) + 1.0f);
    float bmax = fmaxf(fmaxf(b.x, b.y), fmaxf(b.z, b.w));

    // rare tail: shells dk >= 2 (P(warp enters) ~ 6%)
    if (bmax > 4.0f) {
        int dk = 2;
        float dk2 = 4.0f;            // dk^2, carried forward
        while (true) {
            int u = refl(i - dk), d = refl(i + dk);
            float4 vu = __ldg((const float4*)(g2 + u * WW + j4));
            float4 vd = __ldg((const float4*)(g2 + d * WW + j4));
            b.x = fminf(b.x, fminf(vu.x, vd.x) + dk2);
            b.y = fminf(b.y, fminf(vu.y, vd.y) + dk2);
            b.z = fminf(b.z, fminf(vu.z, vd.z) + dk2);
            b.w = fminf(b.w, fminf(vu.w, vd.w) + dk2);
            bmax = fmaxf(fmaxf(b.x, b.y), fmaxf(b.z, b.w));
            dk++;
            if (dk >= HH) break;
            dk2 = (float)(dk * dk);  // next shell's dk^2 (single compute)
            if (dk2 >= bmax) break;  // exact exit bound
        }
    }

    // cross-weighting: pred_dt weighted by target edge mask and vice versa
    float val = (e.x ? sqrtf(b.x) : 0.0f) + (e.y ? sqrtf(b.y) : 0.0f)
              + (e.z ? sqrtf(b.z) : 0.0f) + (e.w ? sqrtf(b.w) : 0.0f);

    // deterministic block reduction: per-warp shfl tree + fixed-order sum
    #pragma unroll
    for (int d = 16; d > 0; d >>= 1)
        val += __shfl_down_sync(FULLMASK, val, d);

    __shared__ float wsum[8];
    __shared__ bool is_last;
    int lane = tx & 31;
    int wid = tx >> 5;
    if (lane == 0) wsum[wid] = val;
    __syncthreads();
    if (tx == 0) {
        float s = 0.0f;
        #pragma unroll
        for (int w = 0; w < 8; w++) s += wsum[w];
        int bid = blockIdx.y * gridDim.x + blockIdx.x;
        d_partials[bid] = s;
        __threadfence();                     // partial visible before count
        int old = atomicAdd(&d_count, 1);
        is_last = (old == TOTB - 1);
    }
    __syncthreads();

    // ---- last block: deterministic fixed-order final reduction + sigmoid ----
    if (is_last) {
        __threadfence();                     // acquire all partials
        __shared__ double sh[256];
        double s = 0.0;
        for (int k = tx; k < TOTB; k += 256)
            s += (double)d_partials[k];
        sh[tx] = s;
        __syncthreads();
        for (int st = 128; st > 0; st >>= 1) {
            if (tx < st) sh[tx] += sh[tx + st];
            __syncthreads();
        }
        if (tx == 0) {
            double loss = sh[0] / (2.0 * (double)HH * (double)WW);
            out[0] = (float)(1.0 / (1.0 + exp(-loss)));
            d_count = 0;                     // reset for next graph replay
        }
    }
}

// ---------------------------------------------------------------------------
extern "C" void kernel_launch(void* const* d_in, const int* in_sizes, int n_in,
                              void* d_out, int out_size) {
    const float* pred = (const float*)d_in[0];
    const float* targ = (const float*)d_in[1];
    float* out = (float*)d_out;

    // one 256-thread block per (row, image) for both passes
    edges_row_dist_kernel<<<dim3(HH, 2), 256>>>(pred, targ);
    edt_loss_kernel<<<dim3(HH, 2), 256>>>(out);
}